// round 13
// baseline (speedup 1.0000x reference)
#include <cuda_runtime.h>

typedef unsigned long long u64;

// ---------------- packed f32x2 helpers (sm_103a) ----------------
__device__ __forceinline__ u64 pk2(float lo, float hi) {
    u64 r;
    asm("mov.b64 %0, {%1, %2};" : "=l"(r) : "f"(lo), "f"(hi));
    return r;
}
__device__ __forceinline__ void unpk2(u64 v, float& lo, float& hi) {
    asm("mov.b64 {%0, %1}, %2;" : "=f"(lo), "=f"(hi) : "l"(v));
}
__device__ __forceinline__ u64 mul2(u64 a, u64 b) {
    u64 r;
    asm("mul.rn.f32x2 %0, %1, %2;" : "=l"(r) : "l"(a), "l"(b));
    return r;
}
__device__ __forceinline__ u64 fma2(u64 a, u64 b, u64 c) {
    u64 r;
    asm("fma.rn.f32x2 %0, %1, %2, %3;" : "=l"(r) : "l"(a), "l"(b), "l"(c));
    return r;
}

// Heisenberg-picture constants. Each feature <Z_q> is an exact multilinear
// polynomial in (1, cos x_i, sin x_i); Pauli back-propagation gives the sparse
// monomial support (6/5/6/13 terms). Coefficients extracted numerically in
// setup_kernel via exact 3^4-grid interpolation.
struct Consts {
    u64 k0[6];
    u64 k1[5];
    u64 k2[6];
    u64 k3[13];
    u64 w0[4], w1[4];   // head rows (packed)
    u64 b0, b1;         // bias + constant-term fold
};

__device__ Consts g_scratch;
__constant__ Consts c_consts;

__global__ void setup_kernel(const float* __restrict__ weights,
                             const float* __restrict__ W,
                             const float* __restrict__ b) {
    __shared__ float G[4][81];
    int tid = threadIdx.x;

    // --- 1. simulate circuit features on the 3^4 grid x_i in {0, pi/2, pi} ---
    if (tid < 81) {
        const float HP = 1.57079632679489662f;  // pi/2
        int d0 = tid / 27, d1 = (tid / 9) % 3, d2 = (tid / 3) % 3, d3 = tid % 3;
        float xg[4] = { d0 * HP, d1 * HP, d2 * HP, d3 * HP };
        float cc[4], ss[4];
        for (int i = 0; i < 4; ++i) {
            float h = 0.5f * xg[i];
            cc[i] = cosf(h);
            ss[i] = sinf(h);
        }
        float st[16];
        for (int s = 0; s < 16; ++s) {
            float v = 1.0f;
            for (int i = 0; i < 4; ++i) v *= ((s >> (3 - i)) & 1) ? ss[i] : cc[i];
            st[s] = v;
        }
        for (int l = 0; l < 2; ++l) {
            for (int i = 0; i < 4; ++i) {               // CNOT ring
                int c = i, tq = (i + 1) & 3;
                int mc = 1 << (3 - c), mt = 1 << (3 - tq);
                for (int s = 0; s < 16; ++s)
                    if ((s & mc) && !(s & mt)) {
                        float tmp = st[s]; st[s] = st[s | mt]; st[s | mt] = tmp;
                    }
            }
            for (int i = 0; i < 4; ++i) {               // RY(weights[l][i])
                float h = 0.5f * weights[l * 4 + i];
                float c = cosf(h), sn = sinf(h);
                int m = 1 << (3 - i);
                for (int s = 0; s < 16; ++s)
                    if (!(s & m)) {
                        float a0 = st[s], a1 = st[s | m];
                        st[s]     = c * a0 - sn * a1;
                        st[s | m] = sn * a0 + c * a1;
                    }
            }
        }
        for (int q = 0; q < 4; ++q) {
            int m = 1 << (3 - q);
            float f = 0.0f;
            for (int s = 0; s < 16; ++s) {
                float p = st[s] * st[s];
                f += (s & m) ? -p : p;
            }
            G[q][tid] = f;
        }
    }
    __syncthreads();

    // --- 2. exact per-axis inverse transform: values(0,pi/2,pi) -> (1,cos,sin) coeffs ---
    for (int a = 0; a < 4; ++a) {
        int stride = (a == 0) ? 27 : (a == 1) ? 9 : (a == 2) ? 3 : 1;
        if (tid < 108) {
            int q = tid / 27, line = tid % 27;
            int e0 = line / 9, e1 = (line / 3) % 3, e2 = line % 3;
            int digs[4];
            int ej[3] = { e0, e1, e2 };
            int j = 0;
            for (int pos = 0; pos < 4; ++pos)
                digs[pos] = (pos == a) ? 0 : ej[j++];
            int p0 = digs[0] * 27 + digs[1] * 9 + digs[2] * 3 + digs[3];
            float g0 = G[q][p0], g1 = G[q][p0 + stride], g2 = G[q][p0 + 2 * stride];
            float k1v = 0.5f * (g0 + g2);
            float kcv = 0.5f * (g0 - g2);
            float ksv = g1 - k1v;
            G[q][p0] = k1v;
            G[q][p0 + stride] = kcv;
            G[q][p0 + 2 * stride] = ksv;
        }
        __syncthreads();
    }

    // --- 3. pick sparse monomial coefficients + fold head ---
    if (tid == 0) {
        const int i0[6]  = { 37, 77, 25, 54, 60, 31 };
        const int i1[5]  = { 31, 60, 20, 44, 3 };
        const int i2[6]  = { 10, 52, 75, 56, 78, 1 };
        const int i3[13] = { 30, 17, 47, 67, 5, 42, 61, 18, 9, 51, 76, 38, 26 };
        for (int i = 0; i < 6; ++i)  g_scratch.k0[i] = pk2(G[0][i0[i]], G[0][i0[i]]);
        for (int i = 0; i < 5; ++i)  g_scratch.k1[i] = pk2(G[1][i1[i]], G[1][i1[i]]);
        for (int i = 0; i < 6; ++i)  g_scratch.k2[i] = pk2(G[2][i2[i]], G[2][i2[i]]);
        for (int i = 0; i < 13; ++i) g_scratch.k3[i] = pk2(G[3][i3[i]], G[3][i3[i]]);
        for (int q = 0; q < 4; ++q) {
            g_scratch.w0[q] = pk2(W[q], W[q]);
            g_scratch.w1[q] = pk2(W[4 + q], W[4 + q]);
        }
        float cb0 = b[0] + W[0] * G[0][0] + W[1] * G[1][0] + W[2] * G[2][0] + W[3] * G[3][0];
        float cb1 = b[1] + W[4] * G[0][0] + W[5] * G[1][0] + W[6] * G[2][0] + W[7] * G[3][0];
        g_scratch.b0 = pk2(cb0, cb0);
        g_scratch.b1 = pk2(cb1, cb1);
    }
}

// Evaluate both outputs for one packed 2-sample stream from trig packs.
__device__ __forceinline__ void eval_stream(
    u64 C0, u64 S0, u64 C1, u64 S1, u64 C2, u64 S2, u64 C3, u64 S3,
    u64& o0, u64& o1)
{
    // Shared pair products.
    u64 c0c1 = mul2(C0, C1), s0s1 = mul2(S0, S1);
    u64 c2c3 = mul2(C2, C3), s2s3 = mul2(S2, S3);
    u64 s1s2 = mul2(S1, S2), s1s3 = mul2(S1, S3);
    u64 s0s2 = mul2(S0, S2), c1c3 = mul2(C1, C3);
    u64 c0c2 = mul2(C0, C2), c0s1 = mul2(C0, S1);
    u64 c2s3 = mul2(C2, S3), s0s3 = mul2(S0, S3);

    u64 m6v = mul2(c0c2, C3);            // c0c2c3 (shared F0/F1)
    u64 c0s1s2 = mul2(c0s1, S2);         // shared F2/F3

    // F0: c0c1c3, s0s1c2s3, s1s2c3, s0, s0s2, c0c2c3
    u64 F0 = mul2(c_consts.k0[0], mul2(c0c1, C3));
    F0 = fma2(c_consts.k0[1], mul2(s0s1, c2s3), F0);
    F0 = fma2(c_consts.k0[2], mul2(s1s2, C3), F0);
    F0 = fma2(c_consts.k0[3], S0, F0);
    F0 = fma2(c_consts.k0[4], s0s2, F0);
    F0 = fma2(c_consts.k0[5], m6v, F0);

    // F1: c0c2c3, s0s2, s1s3, c0c1s2s3, c2
    u64 F1 = mul2(c_consts.k1[0], m6v);
    F1 = fma2(c_consts.k1[1], s0s2, F1);
    F1 = fma2(c_consts.k1[2], s1s3, F1);
    F1 = fma2(c_consts.k1[3], mul2(c0c1, s2s3), F1);
    F1 = fma2(c_consts.k1[4], C2, F1);

    // F2: c1c3, c0s1s2c3, s0s1c2, s0s3, s0s1s2, c3
    u64 F2 = mul2(c_consts.k2[0], c1c3);
    F2 = fma2(c_consts.k2[1], mul2(c0s1s2, C3), F2);
    F2 = fma2(c_consts.k2[2], mul2(s0s1, C2), F2);
    F2 = fma2(c_consts.k2[3], s0s3, F2);
    F2 = fma2(c_consts.k2[4], mul2(s0s1, S2), F2);
    F2 = fma2(c_consts.k2[5], C3, F2);

    // F3: c0c2, c1s2s3, c0s1s3, s0c1c2c3, c2s3, c0c1s2, s0s2c3,
    //     s1, c1, c0s1s2, s0s1c2c3, c0c1s3, s1s2s3
    u64 F3 = mul2(c_consts.k3[0], c0c2);
    F3 = fma2(c_consts.k3[1], mul2(C1, s2s3), F3);
    F3 = fma2(c_consts.k3[2], mul2(c0s1, S3), F3);
    F3 = fma2(c_consts.k3[3], mul2(S0, mul2(C1, c2c3)), F3);
    F3 = fma2(c_consts.k3[4], c2s3, F3);
    F3 = fma2(c_consts.k3[5], mul2(c0c1, S2), F3);
    F3 = fma2(c_consts.k3[6], mul2(s0s2, C3), F3);
    F3 = fma2(c_consts.k3[7], S1, F3);
    F3 = fma2(c_consts.k3[8], C1, F3);
    F3 = fma2(c_consts.k3[9], c0s1s2, F3);
    F3 = fma2(c_consts.k3[10], mul2(s0s1, c2c3), F3);
    F3 = fma2(c_consts.k3[11], mul2(c0c1, S3), F3);
    F3 = fma2(c_consts.k3[12], mul2(s1s2, S3), F3);

    o0 = fma2(c_consts.w0[0], F0, c_consts.b0);
    o0 = fma2(c_consts.w0[1], F1, o0);
    o0 = fma2(c_consts.w0[2], F2, o0);
    o0 = fma2(c_consts.w0[3], F3, o0);
    o1 = fma2(c_consts.w1[0], F0, c_consts.b1);
    o1 = fma2(c_consts.w1[1], F1, o1);
    o1 = fma2(c_consts.w1[2], F2, o1);
    o1 = fma2(c_consts.w1[3], F3, o1);
}

// 4 samples per thread: two independent packed streams for ILP.
__global__ __launch_bounds__(128)
void sim_kernel(const float4* __restrict__ x, float4* __restrict__ out, int Bquad) {
    int t = blockIdx.x * blockDim.x + threadIdx.x;
    if (t >= Bquad) return;

    // Front-batched loads (MLP 4).
    float4 xa = x[4 * t];
    float4 xb = x[4 * t + 1];
    float4 xc = x[4 * t + 2];
    float4 xd = x[4 * t + 3];

    // Stream P: samples a,b.  Stream Q: samples c,d.
    float c0a, s0a, c1a, s1a, c2a, s2a, c3a, s3a;
    float c0b, s0b, c1b, s1b, c2b, s2b, c3b, s3b;
    float c0c, s0c, c1c, s1c, c2c, s2c, c3c, s3c;
    float c0d, s0d, c1d, s1d, c2d, s2d, c3d, s3d;
    __sincosf(xa.x, &s0a, &c0a);  __sincosf(xc.x, &s0c, &c0c);
    __sincosf(xa.y, &s1a, &c1a);  __sincosf(xc.y, &s1c, &c1c);
    __sincosf(xa.z, &s2a, &c2a);  __sincosf(xc.z, &s2c, &c2c);
    __sincosf(xa.w, &s3a, &c3a);  __sincosf(xc.w, &s3c, &c3c);
    __sincosf(xb.x, &s0b, &c0b);  __sincosf(xd.x, &s0d, &c0d);
    __sincosf(xb.y, &s1b, &c1b);  __sincosf(xd.y, &s1d, &c1d);
    __sincosf(xb.z, &s2b, &c2b);  __sincosf(xd.z, &s2d, &c2d);
    __sincosf(xb.w, &s3b, &c3b);  __sincosf(xd.w, &s3d, &c3d);

    u64 oP0, oP1, oQ0, oQ1;
    eval_stream(pk2(c0a, c0b), pk2(s0a, s0b), pk2(c1a, c1b), pk2(s1a, s1b),
                pk2(c2a, c2b), pk2(s2a, s2b), pk2(c3a, c3b), pk2(s3a, s3b),
                oP0, oP1);
    eval_stream(pk2(c0c, c0d), pk2(s0c, s0d), pk2(c1c, c1d), pk2(s1c, s1d),
                pk2(c2c, c2d), pk2(s2c, s2d), pk2(c3c, c3d), pk2(s3c, s3d),
                oQ0, oQ1);

    float p0a, p0b, p1a, p1b, q0a, q0b, q1a, q1b;
    unpk2(oP0, p0a, p0b);
    unpk2(oP1, p1a, p1b);
    unpk2(oQ0, q0a, q0b);
    unpk2(oQ1, q1a, q1b);

    out[2 * t]     = make_float4(p0a, p1a, p0b, p1b);
    out[2 * t + 1] = make_float4(q0a, q1a, q0b, q1b);
}

extern "C" void kernel_launch(void* const* d_in, const int* in_sizes, int n_in,
                              void* d_out, int out_size) {
    const float* x       = (const float*)d_in[0];  // (B, 4)
    const float* weights = (const float*)d_in[1];  // (2, 4)
    const float* W       = (const float*)d_in[2];  // (2, 4)
    const float* b       = (const float*)d_in[3];  // (2,)

    int B = in_sizes[0] / 4;
    int Bquad = B / 4;   // B = 2^21, divisible

    setup_kernel<<<1, 128>>>(weights, W, b);

    void* dst = nullptr;
    void* src = nullptr;
    cudaGetSymbolAddress(&dst, c_consts);
    cudaGetSymbolAddress(&src, g_scratch);
    cudaMemcpyAsync(dst, src, sizeof(Consts), cudaMemcpyDeviceToDevice, 0);

    sim_kernel<<<(Bquad + 127) / 128, 128>>>((const float4*)x, (float4*)d_out, Bquad);
}

// round 14
// speedup vs baseline: 1.0075x; 1.0075x over previous
#include <cuda_runtime.h>

typedef unsigned long long u64;

// ---------------- packed f32x2 helpers (sm_103a) ----------------
__device__ __forceinline__ u64 pk2(float lo, float hi) {
    u64 r;
    asm("mov.b64 %0, {%1, %2};" : "=l"(r) : "f"(lo), "f"(hi));
    return r;
}
__device__ __forceinline__ void unpk2(u64 v, float& lo, float& hi) {
    asm("mov.b64 {%0, %1}, %2;" : "=f"(lo), "=f"(hi) : "l"(v));
}
__device__ __forceinline__ u64 mul2(u64 a, u64 b) {
    u64 r;
    asm("mul.rn.f32x2 %0, %1, %2;" : "=l"(r) : "l"(a), "l"(b));
    return r;
}
__device__ __forceinline__ u64 fma2(u64 a, u64 b, u64 c) {
    u64 r;
    asm("fma.rn.f32x2 %0, %1, %2, %3;" : "=l"(r) : "l"(a), "l"(b), "l"(c));
    return r;
}

// Heisenberg-picture constants. Each feature <Z_q> is an exact multilinear
// polynomial in (1, cos x_i, sin x_i); sparse supports (6/5/6/13 terms).
// Coefficients extracted numerically in setup_kernel via exact 3^4-grid
// interpolation.
struct Consts {
    u64 k0[6];
    u64 k1[5];
    u64 k2[6];
    u64 k3[13];
    u64 w0[4], w1[4];   // head rows (packed)
    u64 b0, b1;         // bias + constant-term fold
};

__device__ Consts g_scratch;
__constant__ Consts c_consts;

__global__ void setup_kernel(const float* __restrict__ weights,
                             const float* __restrict__ W,
                             const float* __restrict__ b) {
    __shared__ float G[4][81];
    int tid = threadIdx.x;

    // --- 1. simulate circuit features on the 3^4 grid x_i in {0, pi/2, pi} ---
    if (tid < 81) {
        const float HP = 1.57079632679489662f;  // pi/2
        int d0 = tid / 27, d1 = (tid / 9) % 3, d2 = (tid / 3) % 3, d3 = tid % 3;
        float xg[4] = { d0 * HP, d1 * HP, d2 * HP, d3 * HP };
        float cc[4], ss[4];
        for (int i = 0; i < 4; ++i) {
            float h = 0.5f * xg[i];
            cc[i] = cosf(h);
            ss[i] = sinf(h);
        }
        float st[16];
        for (int s = 0; s < 16; ++s) {
            float v = 1.0f;
            for (int i = 0; i < 4; ++i) v *= ((s >> (3 - i)) & 1) ? ss[i] : cc[i];
            st[s] = v;
        }
        for (int l = 0; l < 2; ++l) {
            for (int i = 0; i < 4; ++i) {               // CNOT ring
                int c = i, tq = (i + 1) & 3;
                int mc = 1 << (3 - c), mt = 1 << (3 - tq);
                for (int s = 0; s < 16; ++s)
                    if ((s & mc) && !(s & mt)) {
                        float tmp = st[s]; st[s] = st[s | mt]; st[s | mt] = tmp;
                    }
            }
            for (int i = 0; i < 4; ++i) {               // RY(weights[l][i])
                float h = 0.5f * weights[l * 4 + i];
                float c = cosf(h), sn = sinf(h);
                int m = 1 << (3 - i);
                for (int s = 0; s < 16; ++s)
                    if (!(s & m)) {
                        float a0 = st[s], a1 = st[s | m];
                        st[s]     = c * a0 - sn * a1;
                        st[s | m] = sn * a0 + c * a1;
                    }
            }
        }
        for (int q = 0; q < 4; ++q) {
            int m = 1 << (3 - q);
            float f = 0.0f;
            for (int s = 0; s < 16; ++s) {
                float p = st[s] * st[s];
                f += (s & m) ? -p : p;
            }
            G[q][tid] = f;
        }
    }
    __syncthreads();

    // --- 2. exact per-axis inverse transform: values(0,pi/2,pi) -> (1,cos,sin) ---
    for (int a = 0; a < 4; ++a) {
        int stride = (a == 0) ? 27 : (a == 1) ? 9 : (a == 2) ? 3 : 1;
        if (tid < 108) {
            int q = tid / 27, line = tid % 27;
            int e0 = line / 9, e1 = (line / 3) % 3, e2 = line % 3;
            int digs[4];
            int ej[3] = { e0, e1, e2 };
            int j = 0;
            for (int pos = 0; pos < 4; ++pos)
                digs[pos] = (pos == a) ? 0 : ej[j++];
            int p0 = digs[0] * 27 + digs[1] * 9 + digs[2] * 3 + digs[3];
            float g0 = G[q][p0], g1 = G[q][p0 + stride], g2 = G[q][p0 + 2 * stride];
            float k1v = 0.5f * (g0 + g2);
            float kcv = 0.5f * (g0 - g2);
            float ksv = g1 - k1v;
            G[q][p0] = k1v;
            G[q][p0 + stride] = kcv;
            G[q][p0 + 2 * stride] = ksv;
        }
        __syncthreads();
    }

    // --- 3. pick sparse monomial coefficients + fold head ---
    if (tid == 0) {
        const int i0[6]  = { 37, 77, 25, 54, 60, 31 };
        const int i1[5]  = { 31, 60, 20, 44, 3 };
        const int i2[6]  = { 10, 52, 75, 56, 78, 1 };
        const int i3[13] = { 30, 17, 47, 67, 5, 42, 61, 18, 9, 51, 76, 38, 26 };
        for (int i = 0; i < 6; ++i)  g_scratch.k0[i] = pk2(G[0][i0[i]], G[0][i0[i]]);
        for (int i = 0; i < 5; ++i)  g_scratch.k1[i] = pk2(G[1][i1[i]], G[1][i1[i]]);
        for (int i = 0; i < 6; ++i)  g_scratch.k2[i] = pk2(G[2][i2[i]], G[2][i2[i]]);
        for (int i = 0; i < 13; ++i) g_scratch.k3[i] = pk2(G[3][i3[i]], G[3][i3[i]]);
        for (int q = 0; q < 4; ++q) {
            g_scratch.w0[q] = pk2(W[q], W[q]);
            g_scratch.w1[q] = pk2(W[4 + q], W[4 + q]);
        }
        float cb0 = b[0] + W[0] * G[0][0] + W[1] * G[1][0] + W[2] * G[2][0] + W[3] * G[3][0];
        float cb1 = b[1] + W[4] * G[0][0] + W[5] * G[1][0] + W[6] * G[2][0] + W[7] * G[3][0];
        g_scratch.b0 = pk2(cb0, cb0);
        g_scratch.b1 = pk2(cb1, cb1);
    }
}

__global__ __launch_bounds__(128)
void sim_kernel(const float4* __restrict__ x, float4* __restrict__ out, int Bpair) {
    int t = blockIdx.x * blockDim.x + threadIdx.x;
    if (t >= Bpair) return;

    float4 xa = x[2 * t];
    float4 xb = x[2 * t + 1];

    float c0a, s0a, c1a, s1a, c2a, s2a, c3a, s3a;
    float c0b, s0b, c1b, s1b, c2b, s2b, c3b, s3b;
    __sincosf(xa.x, &s0a, &c0a);
    __sincosf(xa.y, &s1a, &c1a);
    __sincosf(xa.z, &s2a, &c2a);
    __sincosf(xa.w, &s3a, &c3a);
    __sincosf(xb.x, &s0b, &c0b);
    __sincosf(xb.y, &s1b, &c1b);
    __sincosf(xb.z, &s2b, &c2b);
    __sincosf(xb.w, &s3b, &c3b);

    u64 C0 = pk2(c0a, c0b), S0 = pk2(s0a, s0b);
    u64 C1 = pk2(c1a, c1b), S1 = pk2(s1a, s1b);
    u64 C2 = pk2(c2a, c2b), S2 = pk2(s2a, s2b);
    u64 C3 = pk2(c3a, c3b), S3 = pk2(s3a, s3b);

    // Pair-grouped monomial walk: each pair product is computed right before
    // its uses and dies immediately; all four feature accumulators interleave.
    // Live set ~ 8 packs + 4 accums + 1-2 temps.

    // Singles init.
    u64 F0 = mul2(c_consts.k0[3], S0);                 // s0
    u64 F1 = mul2(c_consts.k1[4], C2);                 // c2
    u64 F2 = mul2(c_consts.k2[5], C3);                 // c3
    u64 F3 = mul2(c_consts.k3[7], S1);                 // s1
    F3 = fma2(c_consts.k3[8], C1, F3);                 // c1

    {   // s0s2 group
        u64 p = mul2(S0, S2);
        F0 = fma2(c_consts.k0[4], p, F0);              // s0s2
        F1 = fma2(c_consts.k1[1], p, F1);              // s0s2
        F3 = fma2(c_consts.k3[6], mul2(p, C3), F3);    // s0s2c3
    }
    {   // c0c2 group
        u64 p = mul2(C0, C2);
        F3 = fma2(c_consts.k3[0], p, F3);              // c0c2
        u64 m = mul2(p, C3);                           // c0c2c3
        F0 = fma2(c_consts.k0[5], m, F0);
        F1 = fma2(c_consts.k1[0], m, F1);
    }
    {   // c2s3 + s0s1 + c2c3 group
        u64 c2s3 = mul2(C2, S3);
        F3 = fma2(c_consts.k3[4], c2s3, F3);           // c2s3
        u64 s0s1 = mul2(S0, S1);
        F0 = fma2(c_consts.k0[1], mul2(s0s1, c2s3), F0);   // s0s1c2s3
        F2 = fma2(c_consts.k2[2], mul2(s0s1, C2), F2);     // s0s1c2
        F2 = fma2(c_consts.k2[4], mul2(s0s1, S2), F2);     // s0s1s2
        u64 c2c3 = mul2(C2, C3);
        F3 = fma2(c_consts.k3[10], mul2(s0s1, c2c3), F3);  // s0s1c2c3
        F3 = fma2(c_consts.k3[3], mul2(S0, mul2(C1, c2c3)), F3);  // s0c1c2c3
    }
    {   // s2s3 + c0c1 group
        u64 s2s3 = mul2(S2, S3);
        F3 = fma2(c_consts.k3[1], mul2(C1, s2s3), F3);     // c1s2s3
        u64 c0c1 = mul2(C0, C1);
        F1 = fma2(c_consts.k1[3], mul2(c0c1, s2s3), F1);   // c0c1s2s3
        F0 = fma2(c_consts.k0[0], mul2(c0c1, C3), F0);     // c0c1c3
        F3 = fma2(c_consts.k3[5], mul2(c0c1, S2), F3);     // c0c1s2
        F3 = fma2(c_consts.k3[11], mul2(c0c1, S3), F3);    // c0c1s3
    }
    {   // c0s1 group
        u64 p = mul2(C0, S1);
        F3 = fma2(c_consts.k3[2], mul2(p, S3), F3);        // c0s1s3
        u64 u = mul2(p, S2);                               // c0s1s2
        F3 = fma2(c_consts.k3[9], u, F3);
        F2 = fma2(c_consts.k2[1], mul2(u, C3), F2);        // c0s1s2c3
    }
    {   // s1s2 group
        u64 p = mul2(S1, S2);
        F0 = fma2(c_consts.k0[2], mul2(p, C3), F0);        // s1s2c3
        F3 = fma2(c_consts.k3[12], mul2(p, S3), F3);       // s1s2s3
    }
    // Remaining pairs with single uses.
    F1 = fma2(c_consts.k1[2], mul2(S1, S3), F1);           // s1s3
    F2 = fma2(c_consts.k2[0], mul2(C1, C3), F2);           // c1c3
    F2 = fma2(c_consts.k2[3], mul2(S0, S3), F2);           // s0s3

    // Head: out_j = b_j' + sum_q W_jq F_q
    u64 o0 = fma2(c_consts.w0[0], F0, c_consts.b0);
    o0 = fma2(c_consts.w0[1], F1, o0);
    o0 = fma2(c_consts.w0[2], F2, o0);
    o0 = fma2(c_consts.w0[3], F3, o0);
    u64 o1 = fma2(c_consts.w1[0], F0, c_consts.b1);
    o1 = fma2(c_consts.w1[1], F1, o1);
    o1 = fma2(c_consts.w1[2], F2, o1);
    o1 = fma2(c_consts.w1[3], F3, o1);

    float o0a, o0b, o1a, o1b;
    unpk2(o0, o0a, o0b);
    unpk2(o1, o1a, o1b);

    out[t] = make_float4(o0a, o1a, o0b, o1b);
}

extern "C" void kernel_launch(void* const* d_in, const int* in_sizes, int n_in,
                              void* d_out, int out_size) {
    const float* x       = (const float*)d_in[0];  // (B, 4)
    const float* weights = (const float*)d_in[1];  // (2, 4)
    const float* W       = (const float*)d_in[2];  // (2, 4)
    const float* b       = (const float*)d_in[3];  // (2,)

    int B = in_sizes[0] / 4;
    int Bpair = B / 2;

    setup_kernel<<<1, 128>>>(weights, W, b);

    void* dst = nullptr;
    void* src = nullptr;
    cudaGetSymbolAddress(&dst, c_consts);
    cudaGetSymbolAddress(&src, g_scratch);
    cudaMemcpyAsync(dst, src, sizeof(Consts), cudaMemcpyDeviceToDevice, 0);

    sim_kernel<<<(Bpair + 127) / 128, 128>>>((const float4*)x, (float4*)d_out, Bpair);
}